// round 2
// baseline (speedup 1.0000x reference)
#include <cuda_runtime.h>
#include <cstdint>

// VQ nearest-codebook: N=16384 vectors (D=64) vs K=8192 codewords.
// score_k = ||c_k||^2 - 2 x.c_k  (||x||^2 irrelevant for argmin)
// FP32 packed-FMA (fma.rn.f32x2) compute, K split 8-way across blocks,
// combined via order-preserving packed atomicMin, then gather.

#define N_VEC 16384
#define DIM   64
#define KCB   8192
#define KSPLIT 8
#define K_PER_BLOCK (KCB / KSPLIT)   // 1024
#define TK    128                    // codewords per smem tile (32 KB)
#define TILES (K_PER_BLOCK / TK)     // 8
#define BT    128                    // threads per block = vectors per block

typedef unsigned long long ull;

__device__ float g_csq[KCB];
__device__ ull   g_key[N_VEC];

// ---- packed f32x2 helpers (sm_100+) ------------------------------------
__device__ __forceinline__ void fma2(ull& d, ull a, ull b) {
    asm("fma.rn.f32x2 %0, %1, %2, %3;" : "=l"(d) : "l"(a), "l"(b), "l"(d));
}
__device__ __forceinline__ float red2(ull v) {
    float lo, hi;
    asm("mov.b64 {%0,%1}, %2;" : "=f"(lo), "=f"(hi) : "l"(v));
    return lo + hi;
}

// ---- kernel 1: codebook squared norms + key init -----------------------
__global__ void vq_prep(const float* __restrict__ cb) {
    int k = blockIdx.x * blockDim.x + threadIdx.x;
    if (k < KCB) {
        const float4* row = reinterpret_cast<const float4*>(cb + (size_t)k * DIM);
        float s = 0.f;
#pragma unroll
        for (int i = 0; i < DIM / 4; ++i) {
            float4 v = row[i];
            s += v.x * v.x + v.y * v.y + v.z * v.z + v.w * v.w;
        }
        g_csq[k] = s;
    }
    if (k < N_VEC) g_key[k] = 0xFFFFFFFFFFFFFFFFull;
}

// ---- kernel 2: main distance scan --------------------------------------
__global__ __launch_bounds__(BT) void vq_main(const float* __restrict__ enc,
                                              const float* __restrict__ cb) {
    __shared__ ulonglong2 sc[TK][DIM / 4];   // 128 * 16 * 16B = 32 KB
    __shared__ float      scsq[TK];

    const int row   = blockIdx.x * BT + threadIdx.x;
    const int kbase = blockIdx.y * K_PER_BLOCK;

    // x vector in registers as 32 packed f32x2
    ull x[DIM / 2];
    const ull* xrow = reinterpret_cast<const ull*>(enc) + (size_t)row * (DIM / 2);
#pragma unroll
    for (int i = 0; i < DIM / 2; ++i) x[i] = xrow[i];

    float bestScore = 3.4e38f;
    int   bestK     = 0;

    for (int t = 0; t < TILES; ++t) {
        const int k0 = kbase + t * TK;

        // cooperative tile load: TK*16 ulonglong2, 128 threads -> 16 each
        const ulonglong2* csrc =
            reinterpret_cast<const ulonglong2*>(cb) + (size_t)k0 * (DIM / 4);
#pragma unroll
        for (int i = 0; i < (TK * DIM / 4) / BT; ++i) {
            int idx = i * BT + threadIdx.x;
            (&sc[0][0])[idx] = csrc[idx];
        }
        if (threadIdx.x < TK) scsq[threadIdx.x] = g_csq[k0 + threadIdx.x];
        __syncthreads();

#pragma unroll 1
        for (int kk = 0; kk < TK; kk += 4) {
            ull a0 = 0, a1 = 0, a2 = 0, a3 = 0;
            const ulonglong2* c0 = sc[kk + 0];
            const ulonglong2* c1 = sc[kk + 1];
            const ulonglong2* c2 = sc[kk + 2];
            const ulonglong2* c3 = sc[kk + 3];
#pragma unroll
            for (int d = 0; d < DIM / 4; ++d) {
                ulonglong2 v0 = c0[d];
                ulonglong2 v1 = c1[d];
                ulonglong2 v2 = c2[d];
                ulonglong2 v3 = c3[d];
                ull xa = x[2 * d], xb = x[2 * d + 1];
                fma2(a0, xa, v0.x); fma2(a0, xb, v0.y);
                fma2(a1, xa, v1.x); fma2(a1, xb, v1.y);
                fma2(a2, xa, v2.x); fma2(a2, xb, v2.y);
                fma2(a3, xa, v3.x); fma2(a3, xb, v3.y);
            }
            float s0 = fmaf(-2.f, red2(a0), scsq[kk + 0]);
            float s1 = fmaf(-2.f, red2(a1), scsq[kk + 1]);
            float s2 = fmaf(-2.f, red2(a2), scsq[kk + 2]);
            float s3 = fmaf(-2.f, red2(a3), scsq[kk + 3]);
            if (s0 < bestScore) { bestScore = s0; bestK = k0 + kk + 0; }
            if (s1 < bestScore) { bestScore = s1; bestK = k0 + kk + 1; }
            if (s2 < bestScore) { bestScore = s2; bestK = k0 + kk + 2; }
            if (s3 < bestScore) { bestScore = s3; bestK = k0 + kk + 3; }
        }
        __syncthreads();
    }

    // order-preserving (score, idx) key: min over K-splits; ties -> lowest idx
    unsigned int b = __float_as_uint(bestScore);
    b = (b & 0x80000000u) ? ~b : (b | 0x80000000u);
    ull key = ((ull)b << 32) | (unsigned int)bestK;
    atomicMin(&g_key[row], key);
}

// ---- kernel 3: gather winning codewords --------------------------------
__global__ void vq_gather(const float* __restrict__ cb, float* __restrict__ out) {
    int tid = blockIdx.x * blockDim.x + threadIdx.x;  // N_VEC*16 threads
    int row = tid >> 4;
    int i   = tid & 15;
    int k   = (int)(g_key[row] & 0xFFFFFFFFull);
    reinterpret_cast<float4*>(out)[(size_t)row * 16 + i] =
        reinterpret_cast<const float4*>(cb)[(size_t)k * 16 + i];
}

extern "C" void kernel_launch(void* const* d_in, const int* in_sizes, int n_in,
                              void* d_out, int out_size) {
    const float* enc = (const float*)d_in[0];  // (16,32,32,64) fp32
    const float* cb  = (const float*)d_in[1];  // (8192,64) fp32
    float* out = (float*)d_out;
    (void)in_sizes; (void)n_in; (void)out_size;

    vq_prep<<<N_VEC / 256, 256>>>(cb);

    dim3 grid(N_VEC / BT, KSPLIT);
    vq_main<<<grid, BT>>>(enc, cb);

    vq_gather<<<(N_VEC * 16) / 256, 256>>>(cb, out);
}

// round 10
// speedup vs baseline: 2.0437x; 2.0437x over previous
#include <cuda_runtime.h>
#include <cuda_fp16.h>
#include <cstdint>

// VQ nearest-codebook via warp HMMA with DIRECT GLOBAL fragment loads
// (no shared memory in the GEMM at all — bisects the smem/ldmatrix machinery).
// x.c via 3-term exact fp16 split: x1c1 + x1c2 + x2c1  (residual ~4e-6).
// Per-(chunk,half) winners stored as packed (score,idx) keys; exact fp32
// refine pass rescores near-minimal candidates -> fp32-exact final argmin.

#define N_VEC 16384
#define DIM   64
#define KCB   8192
#define MT    128
#define NT    128              // codewords per chunk
#define CHUNKS 64
#define NCTA  128
#define THREADS 256
#define KEYS_PER_ROW 128       // CHUNKS * 2 (wn halves)

typedef unsigned long long ull;

__device__ __align__(16) __half g_x1[N_VEC * DIM];
__device__ __align__(16) __half g_x2[N_VEC * DIM];
__device__ __align__(16) __half g_c1[KCB * DIM];
__device__ __align__(16) __half g_c2[KCB * DIM];
__device__ __align__(16) float  g_csq[KCB];
__device__ ull  g_keys[(size_t)N_VEC * KEYS_PER_ROW];   // 16 MB
__device__ int  g_idx[N_VEC];

// ---------------- helpers ----------------
__device__ __forceinline__ void mma16816(float* d, const uint32_t* a,
                                         uint32_t b0, uint32_t b1, const float* c) {
    asm volatile("mma.sync.aligned.m16n8k16.row.col.f32.f16.f16.f32 "
                 "{%0,%1,%2,%3}, {%4,%5,%6,%7}, {%8,%9}, {%10,%11,%12,%13};"
                 : "=f"(d[0]), "=f"(d[1]), "=f"(d[2]), "=f"(d[3])
                 : "r"(a[0]), "r"(a[1]), "r"(a[2]), "r"(a[3]), "r"(b0), "r"(b1),
                   "f"(c[0]), "f"(c[1]), "f"(c[2]), "f"(c[3]));
}
__device__ __forceinline__ ull packKey(float s, int idx) {
    unsigned int b = __float_as_uint(s);
    b = (b & 0x80000000u) ? ~b : (b | 0x80000000u);
    return ((ull)b << 32) | (unsigned int)idx;
}
__device__ __forceinline__ float unpackScore(ull k) {
    unsigned int b = (unsigned int)(k >> 32);
    b = (b & 0x80000000u) ? (b & 0x7FFFFFFFu) : ~b;
    return __uint_as_float(b);
}

// ---------------- prep: fp16 split ----------------
__global__ void vq_prep_cb(const float* __restrict__ cb) {
    int w   = (blockIdx.x * blockDim.x + threadIdx.x) >> 5;
    int lid = threadIdx.x & 31;
    if (w >= KCB) return;
    float2 v = reinterpret_cast<const float2*>(cb + (size_t)w * DIM)[lid];
    float s = v.x * v.x + v.y * v.y;
#pragma unroll
    for (int o = 16; o > 0; o >>= 1) s += __shfl_xor_sync(0xFFFFFFFFu, s, o);
    if (lid == 0) g_csq[w] = s;
    __half a1 = __float2half_rn(v.x), b1 = __float2half_rn(v.y);
    __half a2 = __float2half_rn(v.x - __half2float(a1));
    __half b2 = __float2half_rn(v.y - __half2float(b1));
    uint32_t p1 = (uint32_t)__half_as_ushort(a1) | ((uint32_t)__half_as_ushort(b1) << 16);
    uint32_t p2 = (uint32_t)__half_as_ushort(a2) | ((uint32_t)__half_as_ushort(b2) << 16);
    reinterpret_cast<uint32_t*>(g_c1)[(size_t)w * 32 + lid] = p1;
    reinterpret_cast<uint32_t*>(g_c2)[(size_t)w * 32 + lid] = p2;
}

__global__ void vq_prep_enc(const float* __restrict__ enc) {
    int w   = (blockIdx.x * blockDim.x + threadIdx.x) >> 5;
    int lid = threadIdx.x & 31;
    if (w >= N_VEC) return;
    float2 v = reinterpret_cast<const float2*>(enc + (size_t)w * DIM)[lid];
    __half a1 = __float2half_rn(v.x), b1 = __float2half_rn(v.y);
    __half a2 = __float2half_rn(v.x - __half2float(a1));
    __half b2 = __float2half_rn(v.y - __half2float(b1));
    uint32_t p1 = (uint32_t)__half_as_ushort(a1) | ((uint32_t)__half_as_ushort(b1) << 16);
    uint32_t p2 = (uint32_t)__half_as_ushort(a2) | ((uint32_t)__half_as_ushort(b2) << 16);
    reinterpret_cast<uint32_t*>(g_x1)[(size_t)w * 32 + lid] = p1;
    reinterpret_cast<uint32_t*>(g_x2)[(size_t)w * 32 + lid] = p2;
}

// ---------------- main: HMMA with global fragments ----------------
__global__ __launch_bounds__(THREADS, 1) void vq_mma() {
    const int tid  = threadIdx.x;
    const int lane = tid & 31;
    const int warp = tid >> 5;
    const int wm   = warp & 3;   // 4 M-groups of 32 rows
    const int wn   = warp >> 2;  // 2 N-groups of 64 codewords
    const int g    = lane >> 2;  // group id (0..7)
    const int t    = lane & 3;   // thread-in-group
    const int rowbase = blockIdx.x * MT;

    const uint32_t* X1 = reinterpret_cast<const uint32_t*>(g_x1); // half2 units
    const uint32_t* X2 = reinterpret_cast<const uint32_t*>(g_x2);
    const uint32_t* C1 = reinterpret_cast<const uint32_t*>(g_c1);
    const uint32_t* C2 = reinterpret_cast<const uint32_t*>(g_c2);

    // A fragments per PTX ISA m16n8k16 table (loaded once, chunk-invariant):
    // reg0: (row g,   col 2t) ; reg1: (row g+8, col 2t)
    // reg2: (row g,   col 2t+8) ; reg3: (row g+8, col 2t+8)
    uint32_t a1[2][4][4], a2[2][4][4];
#pragma unroll
    for (int m = 0; m < 2; ++m) {
        const int r0 = rowbase + wm * 32 + m * 16 + g;   // row for reg0/reg2
#pragma unroll
        for (int k = 0; k < 4; ++k) {
            const int b = r0 * 32 + k * 8 + t;           // uint32 units (32 per row)
            a1[m][k][0] = X1[b];
            a1[m][k][1] = X1[b + 256];                   // +8 rows
            a1[m][k][2] = X1[b + 4];                     // +8 cols
            a1[m][k][3] = X1[b + 260];
            a2[m][k][0] = X2[b];
            a2[m][k][1] = X2[b + 256];
            a2[m][k][2] = X2[b + 4];
            a2[m][k][3] = X2[b + 260];
        }
    }

    for (int ch = 0; ch < CHUNKS; ++ch) {
        const int kb = ch * NT;
        float bestS[4] = {3.4e38f, 3.4e38f, 3.4e38f, 3.4e38f};
        int   bestI[4] = {0, 0, 0, 0};

#pragma unroll
        for (int hf = 0; hf < 2; ++hf) {
            const int nb = kb + wn * 64 + hf * 32;
            float acc[2][4][4];
#pragma unroll
            for (int m = 0; m < 2; ++m)
#pragma unroll
                for (int nt = 0; nt < 4; ++nt)
#pragma unroll
                    for (int e = 0; e < 4; ++e) acc[m][nt][e] = 0.f;

#pragma unroll
            for (int k = 0; k < 4; ++k) {
                // B fragments: b0 = (k=2t, n=g), b1 = (k=2t+8, n=g)
                uint32_t b1r[4][2], b2r[4][2];
#pragma unroll
                for (int nt = 0; nt < 4; ++nt) {
                    const int n   = nb + nt * 8 + g;
                    const int off = n * 32 + k * 8 + t;
                    b1r[nt][0] = __ldg(C1 + off);
                    b1r[nt][1] = __ldg(C1 + off + 4);
                    b2r[nt][0] = __ldg(C2 + off);
                    b2r[nt][1] = __ldg(C2 + off + 4);
                }
#pragma unroll
                for (int nt = 0; nt < 4; ++nt) {
#pragma unroll
                    for (int m = 0; m < 2; ++m) {
                        mma16816(acc[m][nt], a1[m][k], b1r[nt][0], b1r[nt][1], acc[m][nt]);
                        mma16816(acc[m][nt], a2[m][k], b1r[nt][0], b1r[nt][1], acc[m][nt]);
                        mma16816(acc[m][nt], a1[m][k], b2r[nt][0], b2r[nt][1], acc[m][nt]);
                    }
                }
            }

            // epilogue: D map -- c0:(g, 2t) c1:(g, 2t+1) c2:(g+8, 2t) c3:(g+8, 2t+1)
#pragma unroll
            for (int nt = 0; nt < 4; ++nt) {
                const int n0 = nb + nt * 8 + 2 * t;
                const float2 q = *reinterpret_cast<const float2*>(g_csq + n0);
#pragma unroll
                for (int m = 0; m < 2; ++m) {
                    const float s0 = fmaf(-2.f, acc[m][nt][0], q.x);
                    const float s1 = fmaf(-2.f, acc[m][nt][1], q.y);
                    const float s2 = fmaf(-2.f, acc[m][nt][2], q.x);
                    const float s3 = fmaf(-2.f, acc[m][nt][3], q.y);
                    const int lo = m * 2, hi = m * 2 + 1;
                    if (s0 < bestS[lo]) { bestS[lo] = s0; bestI[lo] = n0; }
                    if (s1 < bestS[lo]) { bestS[lo] = s1; bestI[lo] = n0 + 1; }
                    if (s2 < bestS[hi]) { bestS[hi] = s2; bestI[hi] = n0; }
                    if (s3 < bestS[hi]) { bestS[hi] = s3; bestI[hi] = n0 + 1; }
                }
            }
        }

        // per-chunk quad reduce; each (row, warp-half) writes its own key slot
#pragma unroll
        for (int slot = 0; slot < 4; ++slot) {
            ull key = packKey(bestS[slot], bestI[slot]);
            ull o1 = __shfl_xor_sync(0xFFFFFFFFu, key, 1); if (o1 < key) key = o1;
            ull o2 = __shfl_xor_sync(0xFFFFFFFFu, key, 2); if (o2 < key) key = o2;
            if (t == 0) {
                const int row = rowbase + wm * 32 + (slot >> 1) * 16 + (slot & 1) * 8 + g;
                g_keys[(size_t)row * KEYS_PER_ROW + ch * 2 + wn] = key;
            }
        }
    }
}

// ---------------- refine: exact fp32 rescore of near-minimal candidates ----
__global__ __launch_bounds__(256) void vq_refine(const float* __restrict__ enc,
                                                 const float* __restrict__ cb) {
    __shared__ float sx[8][64];
    const int w    = threadIdx.x >> 5;
    const int lane = threadIdx.x & 31;
    const int row  = blockIdx.x * 8 + w;

    const float2 v = reinterpret_cast<const float2*>(enc + (size_t)row * DIM)[lane];
    sx[w][2 * lane]     = v.x;
    sx[w][2 * lane + 1] = v.y;
    __syncwarp();

    ull k[4];
#pragma unroll
    for (int j = 0; j < 4; ++j) k[j] = g_keys[(size_t)row * KEYS_PER_ROW + j * 32 + lane];

    ull kmin = k[0];
#pragma unroll
    for (int j = 1; j < 4; ++j) if (k[j] < kmin) kmin = k[j];
#pragma unroll
    for (int o = 16; o > 0; o >>= 1) {
        ull x = __shfl_xor_sync(0xFFFFFFFFu, kmin, o);
        if (x < kmin) kmin = x;
    }
    const float smin = unpackScore(kmin);

    ull best = 0xFFFFFFFFFFFFFFFFull;
#pragma unroll
    for (int j = 0; j < 4; ++j) {
        if (unpackScore(k[j]) <= smin + 1e-2f) {
            const int idx = (int)(k[j] & 0xFFFFFFFFull);
            const float* c = cb + (size_t)idx * DIM;
            float dot = 0.f;
#pragma unroll
            for (int d = 0; d < DIM; ++d) dot = fmaf(sx[w][d], __ldg(c + d), dot);
            const float s = fmaf(-2.f, dot, g_csq[idx]);
            const ull kk = packKey(s, idx);
            if (kk < best) best = kk;
        }
    }
#pragma unroll
    for (int o = 16; o > 0; o >>= 1) {
        ull x = __shfl_xor_sync(0xFFFFFFFFu, best, o);
        if (x < best) best = x;
    }
    if (lane == 0) g_idx[row] = (int)(best & 0xFFFFFFFFull);
}

// ---------------- gather ----------------
__global__ void vq_gather(const float* __restrict__ cb, float* __restrict__ out) {
    int tg  = blockIdx.x * blockDim.x + threadIdx.x;   // N_VEC*16
    int row = tg >> 4;
    int i   = tg & 15;
    int kk  = g_idx[row];
    reinterpret_cast<float4*>(out)[(size_t)row * 16 + i] =
        reinterpret_cast<const float4*>(cb)[(size_t)kk * 16 + i];
}

extern "C" void kernel_launch(void* const* d_in, const int* in_sizes, int n_in,
                              void* d_out, int out_size) {
    const float* enc = (const float*)d_in[0];  // (16,32,32,64) fp32
    const float* cb  = (const float*)d_in[1];  // (8192,64) fp32
    float* out = (float*)d_out;
    (void)in_sizes; (void)n_in; (void)out_size;

    vq_prep_cb<<<KCB * 32 / 256, 256>>>(cb);
    vq_prep_enc<<<N_VEC * 32 / 256, 256>>>(enc);
    vq_mma<<<NCTA, THREADS>>>();
    vq_refine<<<N_VEC / 8, 256>>>(enc, cb);
    vq_gather<<<(N_VEC * 16) / 256, 256>>>(cb, out);
}

// round 11
// speedup vs baseline: 3.5090x; 1.7170x over previous
#include <cuda_runtime.h>
#include <cuda_fp16.h>
#include <cstdint>

// VQ nearest-codebook via warp HMMA with direct-global fragment loads.
// This round: codebook stored in FRAGMENT ORDER so B loads are LDG.128
// (32 per chunk per warp instead of 128 scattered LDG.32).
// x.c via 3-term exact fp16 split: x1c1 + x1c2 + x2c1 (residual ~4e-6).
// Per-(chunk,half) winners stored as packed (score,idx) keys; exact fp32
// refine pass rescores near-minimal candidates -> fp32-exact final argmin.

#define N_VEC 16384
#define DIM   64
#define KCB   8192
#define MT    128
#define NT    128              // codewords per chunk
#define CHUNKS 64
#define NCTA  128
#define THREADS 256
#define KEYS_PER_ROW 128       // CHUNKS * 2 (wn halves)

typedef unsigned long long ull;

__device__ __align__(16) __half g_x1[N_VEC * DIM];
__device__ __align__(16) __half g_x2[N_VEC * DIM];
// permuted codebook: per row 64 uint32 = [ c1 frag-order (32) | c2 frag-order (32) ]
// frag-order: index t*8 + k*2 + r  <-  original uint32 index k*8 + 4*r + t
__device__ __align__(16) uint32_t g_pc[(size_t)KCB * 64];
__device__ __align__(16) float  g_csq[KCB];
__device__ ull  g_keys[(size_t)N_VEC * KEYS_PER_ROW];   // 16 MB
__device__ int  g_idx[N_VEC];

// ---------------- helpers ----------------
__device__ __forceinline__ void mma16816(float* d, const uint32_t* a,
                                         uint32_t b0, uint32_t b1, const float* c) {
    asm volatile("mma.sync.aligned.m16n8k16.row.col.f32.f16.f16.f32 "
                 "{%0,%1,%2,%3}, {%4,%5,%6,%7}, {%8,%9}, {%10,%11,%12,%13};"
                 : "=f"(d[0]), "=f"(d[1]), "=f"(d[2]), "=f"(d[3])
                 : "r"(a[0]), "r"(a[1]), "r"(a[2]), "r"(a[3]), "r"(b0), "r"(b1),
                   "f"(c[0]), "f"(c[1]), "f"(c[2]), "f"(c[3]));
}
__device__ __forceinline__ ull packKey(float s, int idx) {
    unsigned int b = __float_as_uint(s);
    b = (b & 0x80000000u) ? ~b : (b | 0x80000000u);
    return ((ull)b << 32) | (unsigned int)idx;
}
__device__ __forceinline__ float unpackScore(ull k) {
    unsigned int b = (unsigned int)(k >> 32);
    b = (b & 0x80000000u) ? (b & 0x7FFFFFFFu) : ~b;
    return __uint_as_float(b);
}

// ---------------- prep: fp16 split ----------------
__global__ void vq_prep_cb(const float* __restrict__ cb) {
    int w   = (blockIdx.x * blockDim.x + threadIdx.x) >> 5;
    int lid = threadIdx.x & 31;          // uint32 index within row (0..31)
    if (w >= KCB) return;
    float2 v = reinterpret_cast<const float2*>(cb + (size_t)w * DIM)[lid];
    float s = v.x * v.x + v.y * v.y;
#pragma unroll
    for (int o = 16; o > 0; o >>= 1) s += __shfl_xor_sync(0xFFFFFFFFu, s, o);
    if (lid == 0) g_csq[w] = s;
    __half a1 = __float2half_rn(v.x), b1 = __float2half_rn(v.y);
    __half a2 = __float2half_rn(v.x - __half2float(a1));
    __half b2 = __float2half_rn(v.y - __half2float(b1));
    uint32_t p1 = (uint32_t)__half_as_ushort(a1) | ((uint32_t)__half_as_ushort(b1) << 16);
    uint32_t p2 = (uint32_t)__half_as_ushort(a2) | ((uint32_t)__half_as_ushort(b2) << 16);
    // lid = k*8 + 4*r + t  ->  perm = t*8 + k*2 + r
    int k = lid >> 3, rem = lid & 7, r = rem >> 2, t = rem & 3;
    int perm = t * 8 + k * 2 + r;
    g_pc[(size_t)w * 64 + perm]      = p1;
    g_pc[(size_t)w * 64 + 32 + perm] = p2;
}

__global__ void vq_prep_enc(const float* __restrict__ enc) {
    int w   = (blockIdx.x * blockDim.x + threadIdx.x) >> 5;
    int lid = threadIdx.x & 31;
    if (w >= N_VEC) return;
    float2 v = reinterpret_cast<const float2*>(enc + (size_t)w * DIM)[lid];
    __half a1 = __float2half_rn(v.x), b1 = __float2half_rn(v.y);
    __half a2 = __float2half_rn(v.x - __half2float(a1));
    __half b2 = __float2half_rn(v.y - __half2float(b1));
    uint32_t p1 = (uint32_t)__half_as_ushort(a1) | ((uint32_t)__half_as_ushort(b1) << 16);
    uint32_t p2 = (uint32_t)__half_as_ushort(a2) | ((uint32_t)__half_as_ushort(b2) << 16);
    reinterpret_cast<uint32_t*>(g_x1)[(size_t)w * 32 + lid] = p1;
    reinterpret_cast<uint32_t*>(g_x2)[(size_t)w * 32 + lid] = p2;
}

// ---------------- main: HMMA with coalesced global fragments ----------------
__global__ __launch_bounds__(THREADS, 1) void vq_mma() {
    const int tid  = threadIdx.x;
    const int lane = tid & 31;
    const int warp = tid >> 5;
    const int wm   = warp & 3;   // 4 M-groups of 32 rows
    const int wn   = warp >> 2;  // 2 N-groups of 64 codewords
    const int g    = lane >> 2;  // group id (0..7)
    const int t    = lane & 3;   // thread-in-group
    const int rowbase = blockIdx.x * MT;

    const uint32_t* X1 = reinterpret_cast<const uint32_t*>(g_x1);
    const uint32_t* X2 = reinterpret_cast<const uint32_t*>(g_x2);

    // A fragments (PTX ISA m16n8k16), loaded once, chunk-invariant
    uint32_t a1[2][4][4], a2[2][4][4];
#pragma unroll
    for (int m = 0; m < 2; ++m) {
        const int r0 = rowbase + wm * 32 + m * 16 + g;
#pragma unroll
        for (int k = 0; k < 4; ++k) {
            const int b = r0 * 32 + k * 8 + t;
            a1[m][k][0] = X1[b];
            a1[m][k][1] = X1[b + 256];
            a1[m][k][2] = X1[b + 4];
            a1[m][k][3] = X1[b + 260];
            a2[m][k][0] = X2[b];
            a2[m][k][1] = X2[b + 256];
            a2[m][k][2] = X2[b + 4];
            a2[m][k][3] = X2[b + 260];
        }
    }

    for (int ch = 0; ch < CHUNKS; ++ch) {
        const int kb = ch * NT;
        float bestS[4] = {3.4e38f, 3.4e38f, 3.4e38f, 3.4e38f};
        int   bestI[4] = {0, 0, 0, 0};

#pragma unroll
        for (int hf = 0; hf < 2; ++hf) {
            const int nb = kb + wn * 64 + hf * 32;

            // batched coalesced B loads for this half-chunk: 16x LDG.128
            uint4 q1[4][2], q2[4][2];
#pragma unroll
            for (int nt = 0; nt < 4; ++nt) {
                const int n = nb + nt * 8 + g;
                const uint4* P = reinterpret_cast<const uint4*>(
                    g_pc + (size_t)n * 64 + t * 8);
                q1[nt][0] = __ldg(P);
                q1[nt][1] = __ldg(P + 1);
                q2[nt][0] = __ldg(P + 8);
                q2[nt][1] = __ldg(P + 9);
            }

            float acc[2][4][4];
#pragma unroll
            for (int m = 0; m < 2; ++m)
#pragma unroll
                for (int nt = 0; nt < 4; ++nt)
#pragma unroll
                    for (int e = 0; e < 4; ++e) acc[m][nt][e] = 0.f;

#pragma unroll
            for (int k = 0; k < 4; ++k) {
#pragma unroll
                for (int nt = 0; nt < 4; ++nt) {
                    const uint4& u1 = q1[nt][k >> 1];
                    const uint4& u2 = q2[nt][k >> 1];
                    const uint32_t c1b0 = (k & 1) ? u1.z : u1.x;
                    const uint32_t c1b1 = (k & 1) ? u1.w : u1.y;
                    const uint32_t c2b0 = (k & 1) ? u2.z : u2.x;
                    const uint32_t c2b1 = (k & 1) ? u2.w : u2.y;
#pragma unroll
                    for (int m = 0; m < 2; ++m) {
                        mma16816(acc[m][nt], a1[m][k], c1b0, c1b1, acc[m][nt]);
                        mma16816(acc[m][nt], a2[m][k], c1b0, c1b1, acc[m][nt]);
                        mma16816(acc[m][nt], a1[m][k], c2b0, c2b1, acc[m][nt]);
                    }
                }
            }

            // epilogue: D map -- c0:(g,2t) c1:(g,2t+1) c2:(g+8,2t) c3:(g+8,2t+1)
#pragma unroll
            for (int nt = 0; nt < 4; ++nt) {
                const int n0 = nb + nt * 8 + 2 * t;
                const float2 q = *reinterpret_cast<const float2*>(g_csq + n0);
#pragma unroll
                for (int m = 0; m < 2; ++m) {
                    const float s0 = fmaf(-2.f, acc[m][nt][0], q.x);
                    const float s1 = fmaf(-2.f, acc[m][nt][1], q.y);
                    const float s2 = fmaf(-2.f, acc[m][nt][2], q.x);
                    const float s3 = fmaf(-2.f, acc[m][nt][3], q.y);
                    const int lo = m * 2, hi = m * 2 + 1;
                    if (s0 < bestS[lo]) { bestS[lo] = s0; bestI[lo] = n0; }
                    if (s1 < bestS[lo]) { bestS[lo] = s1; bestI[lo] = n0 + 1; }
                    if (s2 < bestS[hi]) { bestS[hi] = s2; bestI[hi] = n0; }
                    if (s3 < bestS[hi]) { bestS[hi] = s3; bestI[hi] = n0 + 1; }
                }
            }
        }

        // per-chunk quad reduce; each (row, warp-half) writes its own key slot
#pragma unroll
        for (int slot = 0; slot < 4; ++slot) {
            ull key = packKey(bestS[slot], bestI[slot]);
            ull o1 = __shfl_xor_sync(0xFFFFFFFFu, key, 1); if (o1 < key) key = o1;
            ull o2 = __shfl_xor_sync(0xFFFFFFFFu, key, 2); if (o2 < key) key = o2;
            if (t == 0) {
                const int row = rowbase + wm * 32 + (slot >> 1) * 16 + (slot & 1) * 8 + g;
                g_keys[(size_t)row * KEYS_PER_ROW + ch * 2 + wn] = key;
            }
        }
    }
}

// ---------------- refine: exact fp32 rescore of near-minimal candidates ----
__global__ __launch_bounds__(256) void vq_refine(const float* __restrict__ enc,
                                                 const float* __restrict__ cb) {
    __shared__ float sx[8][64];
    const int w    = threadIdx.x >> 5;
    const int lane = threadIdx.x & 31;
    const int row  = blockIdx.x * 8 + w;

    const float2 v = reinterpret_cast<const float2*>(enc + (size_t)row * DIM)[lane];
    sx[w][2 * lane]     = v.x;
    sx[w][2 * lane + 1] = v.y;
    __syncwarp();

    ull k[4];
#pragma unroll
    for (int j = 0; j < 4; ++j) k[j] = g_keys[(size_t)row * KEYS_PER_ROW + j * 32 + lane];

    ull kmin = k[0];
#pragma unroll
    for (int j = 1; j < 4; ++j) if (k[j] < kmin) kmin = k[j];
#pragma unroll
    for (int o = 16; o > 0; o >>= 1) {
        ull x = __shfl_xor_sync(0xFFFFFFFFu, kmin, o);
        if (x < kmin) kmin = x;
    }
    const float smin = unpackScore(kmin);

    ull best = 0xFFFFFFFFFFFFFFFFull;
#pragma unroll
    for (int j = 0; j < 4; ++j) {
        if (unpackScore(k[j]) <= smin + 1e-2f) {
            const int idx = (int)(k[j] & 0xFFFFFFFFull);
            const float* c = cb + (size_t)idx * DIM;
            float dot = 0.f;
#pragma unroll
            for (int d = 0; d < DIM; ++d) dot = fmaf(sx[w][d], __ldg(c + d), dot);
            const float s = fmaf(-2.f, dot, g_csq[idx]);
            const ull kk = packKey(s, idx);
            if (kk < best) best = kk;
        }
    }
#pragma unroll
    for (int o = 16; o > 0; o >>= 1) {
        ull x = __shfl_xor_sync(0xFFFFFFFFu, best, o);
        if (x < best) best = x;
    }
    if (lane == 0) g_idx[row] = (int)(best & 0xFFFFFFFFull);
}

// ---------------- gather ----------------
__global__ void vq_gather(const float* __restrict__ cb, float* __restrict__ out) {
    int tg  = blockIdx.x * blockDim.x + threadIdx.x;   // N_VEC*16
    int row = tg >> 4;
    int i   = tg & 15;
    int kk  = g_idx[row];
    reinterpret_cast<float4*>(out)[(size_t)row * 16 + i] =
        reinterpret_cast<const float4*>(cb)[(size_t)kk * 16 + i];
}

extern "C" void kernel_launch(void* const* d_in, const int* in_sizes, int n_in,
                              void* d_out, int out_size) {
    const float* enc = (const float*)d_in[0];  // (16,32,32,64) fp32
    const float* cb  = (const float*)d_in[1];  // (8192,64) fp32
    float* out = (float*)d_out;
    (void)in_sizes; (void)n_in; (void)out_size;

    vq_prep_cb<<<KCB * 32 / 256, 256>>>(cb);
    vq_prep_enc<<<N_VEC * 32 / 256, 256>>>(enc);
    vq_mma<<<NCTA, THREADS>>>();
    vq_refine<<<N_VEC / 8, 256>>>(enc, cb);
    vq_gather<<<(N_VEC * 16) / 256, 256>>>(cb, out);
}

// round 13
// speedup vs baseline: 3.8417x; 1.0948x over previous
#include <cuda_runtime.h>
#include <cuda_fp16.h>
#include <cstdint>

// VQ nearest-codebook via warp HMMA, direct-global fragment loads (validated).
// This round: KSPLIT=8 grid (1024 CTAs -> 99% SM util), CTA-lifetime argmin
// (16 keys/row instead of 128), gather fused into refine.
// x.c via 3-term exact fp16 split: x1c1 + x1c2 + x2c1 (residual ~1e-6 rel).

#define N_VEC 16384
#define DIM   64
#define KCB   8192
#define MT    128
#define NT    128              // codewords per chunk
#define KSPLIT 8
#define CH_PER_CTA 8           // 64 chunks / KSPLIT
#define THREADS 256
#define KEYS_PER_ROW 16        // KSPLIT * 2 (wn halves)

typedef unsigned long long ull;

__device__ __align__(16) __half g_x1[N_VEC * DIM];
__device__ __align__(16) __half g_x2[N_VEC * DIM];
// permuted codebook: per row 64 uint32 = [ c1 frag-order (32) | c2 frag-order (32) ]
// frag-order: index t*8 + k*2 + r  <-  original uint32 index k*8 + 4*r + t
__device__ __align__(16) uint32_t g_pc[(size_t)KCB * 64];
__device__ __align__(16) float  g_csq[KCB];
__device__ ull  g_keys[(size_t)N_VEC * KEYS_PER_ROW];   // 2 MB

// ---------------- helpers ----------------
__device__ __forceinline__ void mma16816(float* d, const uint32_t* a,
                                         uint32_t b0, uint32_t b1, const float* c) {
    asm volatile("mma.sync.aligned.m16n8k16.row.col.f32.f16.f16.f32 "
                 "{%0,%1,%2,%3}, {%4,%5,%6,%7}, {%8,%9}, {%10,%11,%12,%13};"
                 : "=f"(d[0]), "=f"(d[1]), "=f"(d[2]), "=f"(d[3])
                 : "r"(a[0]), "r"(a[1]), "r"(a[2]), "r"(a[3]), "r"(b0), "r"(b1),
                   "f"(c[0]), "f"(c[1]), "f"(c[2]), "f"(c[3]));
}
__device__ __forceinline__ ull packKey(float s, int idx) {
    unsigned int b = __float_as_uint(s);
    b = (b & 0x80000000u) ? ~b : (b | 0x80000000u);
    return ((ull)b << 32) | (unsigned int)idx;
}
__device__ __forceinline__ float unpackScore(ull k) {
    unsigned int b = (unsigned int)(k >> 32);
    b = (b & 0x80000000u) ? (b & 0x7FFFFFFFu) : ~b;
    return __uint_as_float(b);
}

// ---------------- prep: fp16 split ----------------
__global__ void vq_prep_cb(const float* __restrict__ cb) {
    int w   = (blockIdx.x * blockDim.x + threadIdx.x) >> 5;
    int lid = threadIdx.x & 31;          // uint32 index within row (0..31)
    if (w >= KCB) return;
    float2 v = reinterpret_cast<const float2*>(cb + (size_t)w * DIM)[lid];
    float s = v.x * v.x + v.y * v.y;
#pragma unroll
    for (int o = 16; o > 0; o >>= 1) s += __shfl_xor_sync(0xFFFFFFFFu, s, o);
    if (lid == 0) g_csq[w] = s;
    __half a1 = __float2half_rn(v.x), b1 = __float2half_rn(v.y);
    __half a2 = __float2half_rn(v.x - __half2float(a1));
    __half b2 = __float2half_rn(v.y - __half2float(b1));
    uint32_t p1 = (uint32_t)__half_as_ushort(a1) | ((uint32_t)__half_as_ushort(b1) << 16);
    uint32_t p2 = (uint32_t)__half_as_ushort(a2) | ((uint32_t)__half_as_ushort(b2) << 16);
    // lid = k*8 + 4*r + t  ->  perm = t*8 + k*2 + r
    int k = lid >> 3, rem = lid & 7, r = rem >> 2, t = rem & 3;
    int perm = t * 8 + k * 2 + r;
    g_pc[(size_t)w * 64 + perm]      = p1;
    g_pc[(size_t)w * 64 + 32 + perm] = p2;
}

__global__ void vq_prep_enc(const float* __restrict__ enc) {
    int w   = (blockIdx.x * blockDim.x + threadIdx.x) >> 5;
    int lid = threadIdx.x & 31;
    if (w >= N_VEC) return;
    float2 v = reinterpret_cast<const float2*>(enc + (size_t)w * DIM)[lid];
    __half a1 = __float2half_rn(v.x), b1 = __float2half_rn(v.y);
    __half a2 = __float2half_rn(v.x - __half2float(a1));
    __half b2 = __float2half_rn(v.y - __half2float(b1));
    uint32_t p1 = (uint32_t)__half_as_ushort(a1) | ((uint32_t)__half_as_ushort(b1) << 16);
    uint32_t p2 = (uint32_t)__half_as_ushort(a2) | ((uint32_t)__half_as_ushort(b2) << 16);
    reinterpret_cast<uint32_t*>(g_x1)[(size_t)w * 32 + lid] = p1;
    reinterpret_cast<uint32_t*>(g_x2)[(size_t)w * 32 + lid] = p2;
}

// ---------------- main: HMMA with coalesced global fragments ----------------
// grid = (N_VEC/MT) * KSPLIT; blockIdx.x = rowblock*KSPLIT + ks
__global__ __launch_bounds__(THREADS, 1) void vq_mma() {
    const int tid  = threadIdx.x;
    const int lane = tid & 31;
    const int warp = tid >> 5;
    const int wm   = warp & 3;   // 4 M-groups of 32 rows
    const int wn   = warp >> 2;  // 2 N-groups of 64 codewords
    const int g    = lane >> 2;  // group id (0..7)
    const int t    = lane & 3;   // thread-in-group
    const int rowbase = (blockIdx.x >> 3) * MT;
    const int ks      = blockIdx.x & 7;

    const uint32_t* X1 = reinterpret_cast<const uint32_t*>(g_x1);
    const uint32_t* X2 = reinterpret_cast<const uint32_t*>(g_x2);

    // A fragments (PTX ISA m16n8k16), loaded once, chunk-invariant
    uint32_t a1[2][4][4], a2[2][4][4];
#pragma unroll
    for (int m = 0; m < 2; ++m) {
        const int r0 = rowbase + wm * 32 + m * 16 + g;
#pragma unroll
        for (int k = 0; k < 4; ++k) {
            const int b = r0 * 32 + k * 8 + t;
            a1[m][k][0] = X1[b];
            a1[m][k][1] = X1[b + 256];
            a1[m][k][2] = X1[b + 4];
            a1[m][k][3] = X1[b + 260];
            a2[m][k][0] = X2[b];
            a2[m][k][1] = X2[b + 256];
            a2[m][k][2] = X2[b + 4];
            a2[m][k][3] = X2[b + 260];
        }
    }

    float bestS[4] = {3.4e38f, 3.4e38f, 3.4e38f, 3.4e38f};
    int   bestI[4] = {0, 0, 0, 0};

    for (int ch = ks * CH_PER_CTA; ch < ks * CH_PER_CTA + CH_PER_CTA; ++ch) {
        const int kb = ch * NT;
#pragma unroll
        for (int hf = 0; hf < 2; ++hf) {
            const int nb = kb + wn * 64 + hf * 32;

            // batched coalesced B loads for this half-chunk: 16x LDG.128
            uint4 q1[4][2], q2[4][2];
#pragma unroll
            for (int nt = 0; nt < 4; ++nt) {
                const int n = nb + nt * 8 + g;
                const uint4* P = reinterpret_cast<const uint4*>(
                    g_pc + (size_t)n * 64 + t * 8);
                q1[nt][0] = __ldg(P);
                q1[nt][1] = __ldg(P + 1);
                q2[nt][0] = __ldg(P + 8);
                q2[nt][1] = __ldg(P + 9);
            }

            float acc[2][4][4];
#pragma unroll
            for (int m = 0; m < 2; ++m)
#pragma unroll
                for (int nt = 0; nt < 4; ++nt)
#pragma unroll
                    for (int e = 0; e < 4; ++e) acc[m][nt][e] = 0.f;

#pragma unroll
            for (int k = 0; k < 4; ++k) {
#pragma unroll
                for (int nt = 0; nt < 4; ++nt) {
                    const uint4& u1 = q1[nt][k >> 1];
                    const uint4& u2 = q2[nt][k >> 1];
                    const uint32_t c1b0 = (k & 1) ? u1.z : u1.x;
                    const uint32_t c1b1 = (k & 1) ? u1.w : u1.y;
                    const uint32_t c2b0 = (k & 1) ? u2.z : u2.x;
                    const uint32_t c2b1 = (k & 1) ? u2.w : u2.y;
#pragma unroll
                    for (int m = 0; m < 2; ++m) {
                        mma16816(acc[m][nt], a1[m][k], c1b0, c1b1, acc[m][nt]);
                        mma16816(acc[m][nt], a2[m][k], c1b0, c1b1, acc[m][nt]);
                        mma16816(acc[m][nt], a1[m][k], c2b0, c2b1, acc[m][nt]);
                    }
                }
            }

            // epilogue: D map -- c0:(g,2t) c1:(g,2t+1) c2:(g+8,2t) c3:(g+8,2t+1)
#pragma unroll
            for (int nt = 0; nt < 4; ++nt) {
                const int n0 = nb + nt * 8 + 2 * t;
                const float2 q = *reinterpret_cast<const float2*>(g_csq + n0);
#pragma unroll
                for (int m = 0; m < 2; ++m) {
                    const float s0 = fmaf(-2.f, acc[m][nt][0], q.x);
                    const float s1 = fmaf(-2.f, acc[m][nt][1], q.y);
                    const float s2 = fmaf(-2.f, acc[m][nt][2], q.x);
                    const float s3 = fmaf(-2.f, acc[m][nt][3], q.y);
                    const int lo = m * 2, hi = m * 2 + 1;
                    if (s0 < bestS[lo]) { bestS[lo] = s0; bestI[lo] = n0; }
                    if (s1 < bestS[lo]) { bestS[lo] = s1; bestI[lo] = n0 + 1; }
                    if (s2 < bestS[hi]) { bestS[hi] = s2; bestI[hi] = n0; }
                    if (s3 < bestS[hi]) { bestS[hi] = s3; bestI[hi] = n0 + 1; }
                }
            }
        }
    }

    // CTA-lifetime quad reduce; one key per (row, ks, wn)
#pragma unroll
    for (int slot = 0; slot < 4; ++slot) {
        ull key = packKey(bestS[slot], bestI[slot]);
        ull o1 = __shfl_xor_sync(0xFFFFFFFFu, key, 1); if (o1 < key) key = o1;
        ull o2 = __shfl_xor_sync(0xFFFFFFFFu, key, 2); if (o2 < key) key = o2;
        if (t == 0) {
            const int row = rowbase + wm * 32 + (slot >> 1) * 16 + (slot & 1) * 8 + g;
            g_keys[(size_t)row * KEYS_PER_ROW + ks * 2 + wn] = key;
        }
    }
}

// ------- refine: exact fp32 rescore of near-minimal candidates + gather -----
__global__ __launch_bounds__(256) void vq_refine(const float* __restrict__ enc,
                                                 const float* __restrict__ cb,
                                                 float* __restrict__ out) {
    __shared__ float sx[8][64];
    const int w    = threadIdx.x >> 5;
    const int lane = threadIdx.x & 31;
    const int row  = blockIdx.x * 8 + w;

    const float2 v = reinterpret_cast<const float2*>(enc + (size_t)row * DIM)[lane];
    sx[w][2 * lane]     = v.x;
    sx[w][2 * lane + 1] = v.y;
    __syncwarp();

    ull k = 0xFFFFFFFFFFFFFFFFull;
    if (lane < KEYS_PER_ROW) k = g_keys[(size_t)row * KEYS_PER_ROW + lane];

    ull kmin = k;
#pragma unroll
    for (int o = 16; o > 0; o >>= 1) {
        ull x = __shfl_xor_sync(0xFFFFFFFFu, kmin, o);
        if (x < kmin) kmin = x;
    }
    const float smin = unpackScore(kmin);

    ull best = 0xFFFFFFFFFFFFFFFFull;
    if (lane < KEYS_PER_ROW && unpackScore(k) <= smin + 1e-2f) {
        const int idx = (int)(k & 0xFFFFFFFFull);
        const float* c = cb + (size_t)idx * DIM;
        float dot = 0.f;
#pragma unroll
        for (int d = 0; d < DIM; ++d) dot = fmaf(sx[w][d], __ldg(c + d), dot);
        const float s = fmaf(-2.f, dot, g_csq[idx]);
        best = packKey(s, idx);
    }
#pragma unroll
    for (int o = 16; o > 0; o >>= 1) {
        ull x = __shfl_xor_sync(0xFFFFFFFFu, best, o);
        if (x < best) best = x;
    }
    const int kwin = (int)(best & 0xFFFFFFFFull);

    // fused gather: 16 lanes write the row's 64 floats
    if (lane < 16)
        reinterpret_cast<float4*>(out)[(size_t)row * 16 + lane] =
            reinterpret_cast<const float4*>(cb)[(size_t)kwin * 16 + lane];
}

extern "C" void kernel_launch(void* const* d_in, const int* in_sizes, int n_in,
                              void* d_out, int out_size) {
    const float* enc = (const float*)d_in[0];  // (16,32,32,64) fp32
    const float* cb  = (const float*)d_in[1];  // (8192,64) fp32
    float* out = (float*)d_out;
    (void)in_sizes; (void)n_in; (void)out_size;

    vq_prep_cb<<<KCB * 32 / 256, 256>>>(cb);
    vq_prep_enc<<<N_VEC * 32 / 256, 256>>>(enc);
    vq_mma<<<(N_VEC / MT) * KSPLIT, THREADS>>>();
    vq_refine<<<N_VEC / 8, 256>>>(enc, cb, out);
}

// round 15
// speedup vs baseline: 4.1338x; 1.0760x over previous
#include <cuda_runtime.h>
#include <cuda_fp16.h>
#include <cstdint>

// VQ nearest-codebook via warp HMMA, direct-global fragment loads (validated).
// This round: rolling register prefetch at QUARTER-chunk granularity (2 n-tiles)
// -- load quarter i+1 while MMA-ing quarter i; register-neutral vs round 11.
// x.c via 3-term exact fp16 split: x1c1 + x1c2 + x2c1 (residual ~1e-6 rel).

#define N_VEC 16384
#define DIM   64
#define KCB   8192
#define MT    128
#define NT    128              // codewords per chunk
#define KSPLIT 8
#define CH_PER_CTA 8           // 64 chunks / KSPLIT
#define QPC    (CH_PER_CTA * 4)  // quarters per CTA = 32 (16 codewords each)
#define THREADS 256
#define KEYS_PER_ROW 16        // KSPLIT * 2 (wn halves)

typedef unsigned long long ull;

__device__ __align__(16) __half g_x1[N_VEC * DIM];
__device__ __align__(16) __half g_x2[N_VEC * DIM];
// permuted codebook: per row 64 uint32 = [ c1 frag-order (32) | c2 frag-order (32) ]
// frag-order: index t*8 + k*2 + r  <-  original uint32 index k*8 + 4*r + t
__device__ __align__(16) uint32_t g_pc[(size_t)KCB * 64];
__device__ __align__(16) float  g_csq[KCB];
__device__ ull  g_keys[(size_t)N_VEC * KEYS_PER_ROW];   // 2 MB

// ---------------- helpers ----------------
__device__ __forceinline__ void mma16816(float* d, const uint32_t* a,
                                         uint32_t b0, uint32_t b1, const float* c) {
    asm volatile("mma.sync.aligned.m16n8k16.row.col.f32.f16.f16.f32 "
                 "{%0,%1,%2,%3}, {%4,%5,%6,%7}, {%8,%9}, {%10,%11,%12,%13};"
                 : "=f"(d[0]), "=f"(d[1]), "=f"(d[2]), "=f"(d[3])
                 : "r"(a[0]), "r"(a[1]), "r"(a[2]), "r"(a[3]), "r"(b0), "r"(b1),
                   "f"(c[0]), "f"(c[1]), "f"(c[2]), "f"(c[3]));
}
__device__ __forceinline__ ull packKey(float s, int idx) {
    unsigned int b = __float_as_uint(s);
    b = (b & 0x80000000u) ? ~b : (b | 0x80000000u);
    return ((ull)b << 32) | (unsigned int)idx;
}
__device__ __forceinline__ float unpackScore(ull k) {
    unsigned int b = (unsigned int)(k >> 32);
    b = (b & 0x80000000u) ? (b & 0x7FFFFFFFu) : ~b;
    return __uint_as_float(b);
}

// ---------------- prep: fp16 split (cb + enc fused) ----------------
__global__ void vq_prep(const float* __restrict__ cb, const float* __restrict__ enc) {
    int w   = (blockIdx.x * blockDim.x + threadIdx.x) >> 5;
    int lid = threadIdx.x & 31;
    const bool isCb = (w < KCB);
    const float* src = isCb ? cb : enc;
    const int row = isCb ? w : (w - KCB);
    if (!isCb && row >= N_VEC) return;

    float2 v = reinterpret_cast<const float2*>(src + (size_t)row * DIM)[lid];
    __half a1 = __float2half_rn(v.x), b1 = __float2half_rn(v.y);
    __half a2 = __float2half_rn(v.x - __half2float(a1));
    __half b2 = __float2half_rn(v.y - __half2float(b1));
    uint32_t p1 = (uint32_t)__half_as_ushort(a1) | ((uint32_t)__half_as_ushort(b1) << 16);
    uint32_t p2 = (uint32_t)__half_as_ushort(a2) | ((uint32_t)__half_as_ushort(b2) << 16);

    if (isCb) {
        float s = v.x * v.x + v.y * v.y;
#pragma unroll
        for (int o = 16; o > 0; o >>= 1) s += __shfl_xor_sync(0xFFFFFFFFu, s, o);
        if (lid == 0) g_csq[row] = s;
        // lid = k*8 + 4*r + t  ->  perm = t*8 + k*2 + r
        int k = lid >> 3, rem = lid & 7, r = rem >> 2, t = rem & 3;
        int perm = t * 8 + k * 2 + r;
        g_pc[(size_t)row * 64 + perm]      = p1;
        g_pc[(size_t)row * 64 + 32 + perm] = p2;
    } else {
        reinterpret_cast<uint32_t*>(g_x1)[(size_t)row * 32 + lid] = p1;
        reinterpret_cast<uint32_t*>(g_x2)[(size_t)row * 32 + lid] = p2;
    }
}

// ---------------- main: HMMA, rolling quarter-chunk prefetch ----------------
// grid = (N_VEC/MT) * KSPLIT; blockIdx.x = rowblock*KSPLIT + ks
struct QBuf { uint4 c1[2][2]; uint4 c2[2][2]; };   // 16 uint4 = 32 regs

__global__ __launch_bounds__(THREADS, 1) void vq_mma() {
    const int tid  = threadIdx.x;
    const int lane = tid & 31;
    const int warp = tid >> 5;
    const int wm   = warp & 3;   // 4 M-groups of 32 rows
    const int wn   = warp >> 2;  // 2 N-groups of 64 codewords
    const int g    = lane >> 2;  // group id (0..7)
    const int t    = lane & 3;   // thread-in-group
    const int rowbase = (blockIdx.x >> 3) * MT;
    const int ks      = blockIdx.x & 7;

    const uint32_t* X1 = reinterpret_cast<const uint32_t*>(g_x1);
    const uint32_t* X2 = reinterpret_cast<const uint32_t*>(g_x2);

    // A fragments (PTX ISA m16n8k16), loaded once, chunk-invariant
    uint32_t a1[2][4][4], a2[2][4][4];
#pragma unroll
    for (int m = 0; m < 2; ++m) {
        const int r0 = rowbase + wm * 32 + m * 16 + g;
#pragma unroll
        for (int k = 0; k < 4; ++k) {
            const int b = r0 * 32 + k * 8 + t;
            a1[m][k][0] = X1[b];
            a1[m][k][1] = X1[b + 256];
            a1[m][k][2] = X1[b + 4];
            a1[m][k][3] = X1[b + 260];
            a2[m][k][0] = X2[b];
            a2[m][k][1] = X2[b + 256];
            a2[m][k][2] = X2[b + 4];
            a2[m][k][3] = X2[b + 260];
        }
    }

    // quarter qi -> codeword base for this warp:
    //   ch = ks*8 + (qi>>2); sub = qi&3 (16-codeword sub-block within wn's 64)
    const int kb0 = ks * CH_PER_CTA * NT + wn * 64;
#define QBASE(qi) (kb0 + ((qi) >> 2) * NT + ((qi) & 3) * 16)

    QBuf buf[2];
    // prime the pipeline: load quarter 0
    {
        const int nbq = QBASE(0);
#pragma unroll
        for (int p = 0; p < 2; ++p) {
            const int n = nbq + p * 8 + g;
            const uint4* P = reinterpret_cast<const uint4*>(g_pc + (size_t)n * 64 + t * 8);
            buf[0].c1[p][0] = __ldg(P);
            buf[0].c1[p][1] = __ldg(P + 1);
            buf[0].c2[p][0] = __ldg(P + 8);
            buf[0].c2[p][1] = __ldg(P + 9);
        }
    }

    float bestS[4] = {3.4e38f, 3.4e38f, 3.4e38f, 3.4e38f};
    int   bestI[4] = {0, 0, 0, 0};

#pragma unroll 4
    for (int qi = 0; qi < QPC; ++qi) {
        const int cur = qi & 1;
        QBuf& q = buf[cur];
        QBuf& nq = buf[cur ^ 1];

        // prefetch next quarter (clamped on last iteration)
        {
            const int nbq = QBASE(qi + 1 < QPC ? qi + 1 : qi);
#pragma unroll
            for (int p = 0; p < 2; ++p) {
                const int n = nbq + p * 8 + g;
                const uint4* P = reinterpret_cast<const uint4*>(g_pc + (size_t)n * 64 + t * 8);
                nq.c1[p][0] = __ldg(P);
                nq.c1[p][1] = __ldg(P + 1);
                nq.c2[p][0] = __ldg(P + 8);
                nq.c2[p][1] = __ldg(P + 9);
            }
        }

        float acc[2][2][4];
#pragma unroll
        for (int m = 0; m < 2; ++m)
#pragma unroll
            for (int p = 0; p < 2; ++p)
#pragma unroll
                for (int e = 0; e < 4; ++e) acc[m][p][e] = 0.f;

#pragma unroll
        for (int k = 0; k < 4; ++k) {
#pragma unroll
            for (int p = 0; p < 2; ++p) {
                const uint4& u1 = q.c1[p][k >> 1];
                const uint4& u2 = q.c2[p][k >> 1];
                const uint32_t c1b0 = (k & 1) ? u1.z : u1.x;
                const uint32_t c1b1 = (k & 1) ? u1.w : u1.y;
                const uint32_t c2b0 = (k & 1) ? u2.z : u2.x;
                const uint32_t c2b1 = (k & 1) ? u2.w : u2.y;
#pragma unroll
                for (int m = 0; m < 2; ++m) {
                    mma16816(acc[m][p], a1[m][k], c1b0, c1b1, acc[m][p]);
                    mma16816(acc[m][p], a2[m][k], c1b0, c1b1, acc[m][p]);
                    mma16816(acc[m][p], a1[m][k], c2b0, c2b1, acc[m][p]);
                }
            }
        }

        // epilogue: D map -- c0:(g,2t) c1:(g,2t+1) c2:(g+8,2t) c3:(g+8,2t+1)
        const int nbq = QBASE(qi);
#pragma unroll
        for (int p = 0; p < 2; ++p) {
            const int n0 = nbq + p * 8 + 2 * t;
            const float2 cq = *reinterpret_cast<const float2*>(g_csq + n0);
#pragma unroll
            for (int m = 0; m < 2; ++m) {
                const float s0 = fmaf(-2.f, acc[m][p][0], cq.x);
                const float s1 = fmaf(-2.f, acc[m][p][1], cq.y);
                const float s2 = fmaf(-2.f, acc[m][p][2], cq.x);
                const float s3 = fmaf(-2.f, acc[m][p][3], cq.y);
                const int lo = m * 2, hi = m * 2 + 1;
                if (s0 < bestS[lo]) { bestS[lo] = s0; bestI[lo] = n0; }
                if (s1 < bestS[lo]) { bestS[lo] = s1; bestI[lo] = n0 + 1; }
                if (s2 < bestS[hi]) { bestS[hi] = s2; bestI[hi] = n0; }
                if (s3 < bestS[hi]) { bestS[hi] = s3; bestI[hi] = n0 + 1; }
            }
        }
    }

    // CTA-lifetime quad reduce; one key per (row, ks, wn)
#pragma unroll
    for (int slot = 0; slot < 4; ++slot) {
        ull key = packKey(bestS[slot], bestI[slot]);
        ull o1 = __shfl_xor_sync(0xFFFFFFFFu, key, 1); if (o1 < key) key = o1;
        ull o2 = __shfl_xor_sync(0xFFFFFFFFu, key, 2); if (o2 < key) key = o2;
        if (t == 0) {
            const int row = rowbase + wm * 32 + (slot >> 1) * 16 + (slot & 1) * 8 + g;
            g_keys[(size_t)row * KEYS_PER_ROW + ks * 2 + wn] = key;
        }
    }
}

// ------- refine: exact fp32 rescore of near-minimal candidates + gather -----
__global__ __launch_bounds__(256) void vq_refine(const float* __restrict__ enc,
                                                 const float* __restrict__ cb,
                                                 float* __restrict__ out) {
    __shared__ float sx[8][64];
    const int w    = threadIdx.x >> 5;
    const int lane = threadIdx.x & 31;
    const int row  = blockIdx.x * 8 + w;

    const float2 v = reinterpret_cast<const float2*>(enc + (size_t)row * DIM)[lane];
    sx[w][2 * lane]     = v.x;
    sx[w][2 * lane + 1] = v.y;
    __syncwarp();

    ull k = 0xFFFFFFFFFFFFFFFFull;
    if (lane < KEYS_PER_ROW) k = g_keys[(size_t)row * KEYS_PER_ROW + lane];

    ull kmin = k;
#pragma unroll
    for (int o = 16; o > 0; o >>= 1) {
        ull x = __shfl_xor_sync(0xFFFFFFFFu, kmin, o);
        if (x < kmin) kmin = x;
    }
    const float smin = unpackScore(kmin);

    ull best = 0xFFFFFFFFFFFFFFFFull;
    if (lane < KEYS_PER_ROW && unpackScore(k) <= smin + 1e-2f) {
        const int idx = (int)(k & 0xFFFFFFFFull);
        const float* c = cb + (size_t)idx * DIM;
        float dot = 0.f;
#pragma unroll
        for (int d = 0; d < DIM; ++d) dot = fmaf(sx[w][d], __ldg(c + d), dot);
        const float s = fmaf(-2.f, dot, g_csq[idx]);
        best = packKey(s, idx);
    }
#pragma unroll
    for (int o = 16; o > 0; o >>= 1) {
        ull x = __shfl_xor_sync(0xFFFFFFFFu, best, o);
        if (x < best) best = x;
    }
    const int kwin = (int)(best & 0xFFFFFFFFull);

    // fused gather: 16 lanes write the row's 64 floats
    if (lane < 16)
        reinterpret_cast<float4*>(out)[(size_t)row * 16 + lane] =
            reinterpret_cast<const float4*>(cb)[(size_t)kwin * 16 + lane];
}

extern "C" void kernel_launch(void* const* d_in, const int* in_sizes, int n_in,
                              void* d_out, int out_size) {
    const float* enc = (const float*)d_in[0];  // (16,32,32,64) fp32
    const float* cb  = (const float*)d_in[1];  // (8192,64) fp32
    float* out = (float*)d_out;
    (void)in_sizes; (void)n_in; (void)out_size;

    vq_prep<<<(KCB + N_VEC) * 32 / 256, 256>>>(cb, enc);
    vq_mma<<<(N_VEC / MT) * KSPLIT, THREADS>>>();
    vq_refine<<<N_VEC / 8, 256>>>(enc, cb, out);
}